// round 5
// baseline (speedup 1.0000x reference)
#include <cuda_runtime.h>

#define N_NODES 50000
#define N_EDGES 800000
#define IN_FEAT 512
#define OUT_FEAT 128

// Scratch (no allocs allowed): intermediate x = feat @ W, and CSR row pointers.
__device__ float g_x[(size_t)N_NODES * OUT_FEAT];   // 25.6 MB
__device__ int   g_row_ptr[N_NODES + 1];

// ---------------------------------------------------------------------------
// Kernel 1: fp32 SGEMM  C[M,128] = A[M,512] * B[512,128]
// 128x128 block tile, BK=16, 8x8 thread tile, 256 threads.
// ---------------------------------------------------------------------------
__global__ __launch_bounds__(256) void gemm_kernel(const float* __restrict__ A,
                                                   const float* __restrict__ B,
                                                   int M) {
    __shared__ float As[16][128];   // [k][m] (transposed store)
    __shared__ float Bs[16][128];   // [k][n]

    const int tid = threadIdx.x;
    const int tx = tid & 15;        // 0..15 (n-direction)
    const int ty = tid >> 4;        // 0..15 (m-direction)
    const int block_row = blockIdx.x * 128;

    float acc[8][8];
#pragma unroll
    for (int i = 0; i < 8; i++)
#pragma unroll
        for (int j = 0; j < 8; j++) acc[i][j] = 0.0f;

    for (int k0 = 0; k0 < IN_FEAT; k0 += 16) {
        // Load A tile: 128 rows x 16 cols = 512 float4, 2 per thread.
#pragma unroll
        for (int t = 0; t < 2; t++) {
            int pos = tid + t * 256;       // 0..511
            int r   = pos >> 2;            // 0..127
            int c4  = pos & 3;             // which float4 of the 16-wide row
            int grow = block_row + r;
            float4 v = make_float4(0.f, 0.f, 0.f, 0.f);
            if (grow < M)
                v = *(const float4*)(A + (size_t)grow * IN_FEAT + k0 + c4 * 4);
            As[c4 * 4 + 0][r] = v.x;
            As[c4 * 4 + 1][r] = v.y;
            As[c4 * 4 + 2][r] = v.z;
            As[c4 * 4 + 3][r] = v.w;
        }
        // Load B tile: 16 rows x 128 cols = 512 float4, 2 per thread.
#pragma unroll
        for (int t = 0; t < 2; t++) {
            int pos = tid + t * 256;
            int r   = pos >> 5;            // 0..15
            int c4  = pos & 31;            // 0..31
            *(float4*)(&Bs[r][c4 * 4]) =
                *(const float4*)(B + (size_t)(k0 + r) * OUT_FEAT + c4 * 4);
        }
        __syncthreads();

#pragma unroll
        for (int k = 0; k < 16; k++) {
            float rM[8], rN[8];
#pragma unroll
            for (int i = 0; i < 8; i++) rM[i] = As[k][ty * 8 + i];
#pragma unroll
            for (int j = 0; j < 8; j++) rN[j] = Bs[k][tx * 8 + j];
#pragma unroll
            for (int i = 0; i < 8; i++)
#pragma unroll
                for (int j = 0; j < 8; j++)
                    acc[i][j] = fmaf(rM[i], rN[j], acc[i][j]);
        }
        __syncthreads();
    }

    // Store to scratch g_x.
#pragma unroll
    for (int i = 0; i < 8; i++) {
        int grow = block_row + ty * 8 + i;
        if (grow < M) {
#pragma unroll
            for (int j = 0; j < 8; j += 4) {
                float4 v = make_float4(acc[i][j], acc[i][j + 1],
                                       acc[i][j + 2], acc[i][j + 3]);
                *(float4*)(g_x + (size_t)grow * OUT_FEAT + tx * 8 + j) = v;
            }
        }
    }
}

// ---------------------------------------------------------------------------
// Kernel 2: build CSR row_ptr from sorted rows via binary search.
// row_ptr[i] = lower_bound(rows, i); edges of row i = [row_ptr[i], row_ptr[i+1]).
// ---------------------------------------------------------------------------
__global__ void build_rowptr_kernel(const int* __restrict__ rows) {
    int i = blockIdx.x * blockDim.x + threadIdx.x;
    if (i > N_NODES) return;
    int lo = 0, hi = N_EDGES;
    while (lo < hi) {
        int mid = (lo + hi) >> 1;
        if (rows[mid] < i) lo = mid + 1; else hi = mid;
    }
    g_row_ptr[i] = lo;
}

// ---------------------------------------------------------------------------
// Kernel 3: SpMM + multispike. One warp per output row; each lane owns a
// float4 (4 features). Gathers hit L2 (x table is 25.6 MB, fits 126 MB L2).
// ---------------------------------------------------------------------------
__device__ __forceinline__ float multispike(float x) {
    return floorf(fminf(fmaxf(4.0f * x, 0.0f), 4.0f) + 0.5f) * 0.25f;
}

__global__ __launch_bounds__(256) void spmm_kernel(const int* __restrict__ cols,
                                                   const float* __restrict__ ew,
                                                   float* __restrict__ out) {
    int gw   = (blockIdx.x * blockDim.x + threadIdx.x) >> 5;  // global warp = row
    int lane = threadIdx.x & 31;
    if (gw >= N_NODES) return;

    int s = g_row_ptr[gw];
    int e = g_row_ptr[gw + 1];

    const float4* __restrict__ xb = (const float4*)g_x;  // 32 float4 per row

    float ax = 0.f, ay = 0.f, az = 0.f, aw = 0.f;
    int i = s;
    // 2-edge unroll: two independent gathers in flight per iteration.
    for (; i + 1 < e; i += 2) {
        int   c0 = __ldg(cols + i);
        int   c1 = __ldg(cols + i + 1);
        float w0 = __ldg(ew + i);
        float w1 = __ldg(ew + i + 1);
        float4 v0 = __ldg(xb + (size_t)c0 * 32 + lane);
        float4 v1 = __ldg(xb + (size_t)c1 * 32 + lane);
        ax += w0 * v0.x; ay += w0 * v0.y; az += w0 * v0.z; aw += w0 * v0.w;
        ax += w1 * v1.x; ay += w1 * v1.y; az += w1 * v1.z; aw += w1 * v1.w;
    }
    if (i < e) {
        int   c0 = __ldg(cols + i);
        float w0 = __ldg(ew + i);
        float4 v0 = __ldg(xb + (size_t)c0 * 32 + lane);
        ax += w0 * v0.x; ay += w0 * v0.y; az += w0 * v0.z; aw += w0 * v0.w;
    }

    float4 r;
    r.x = multispike(ax);
    r.y = multispike(ay);
    r.z = multispike(az);
    r.w = multispike(aw);
    ((float4*)out)[(size_t)gw * 32 + lane] = r;
}

// ---------------------------------------------------------------------------
// Launch
// ---------------------------------------------------------------------------
extern "C" void kernel_launch(void* const* d_in, const int* in_sizes, int n_in,
                              void* d_out, int out_size) {
    const float* feat   = (const float*)d_in[0];   // [50000, 512]
    const float* weight = (const float*)d_in[1];   // [512, 128]
    const int*   rows   = (const int*)  d_in[2];   // [800000] sorted
    const int*   cols   = (const int*)  d_in[3];   // [800000]
    const float* ew     = (const float*)d_in[4];   // [800000]
    float* out = (float*)d_out;                    // [50000, 128]

    // 1) GEMM into scratch
    int gemm_blocks = (N_NODES + 127) / 128;       // 391
    gemm_kernel<<<gemm_blocks, 256>>>(feat, weight, N_NODES);

    // 2) CSR row pointers (independent of GEMM; default stream serializes, fine)
    build_rowptr_kernel<<<(N_NODES + 1 + 255) / 256, 256>>>(rows);

    // 3) SpMM + activation: one warp per row
    int total_warps = N_NODES;
    int spmm_blocks = (total_warps * 32 + 255) / 256;  // 6250
    spmm_kernel<<<spmm_blocks, 256>>>(cols, ew, out);
}

// round 6
// speedup vs baseline: 1.0122x; 1.0122x over previous
#include <cuda_runtime.h>

#define N_NODES 50000
#define N_EDGES 800000
#define IN_FEAT 512
#define OUT_FEAT 128

// Scratch (no allocs allowed): intermediate x = feat @ W, and CSR row pointers.
__device__ float g_x[(size_t)N_NODES * OUT_FEAT];   // 25.6 MB
__device__ int   g_row_ptr[N_NODES + 1];

// ---------------------------------------------------------------------------
// Packed f32x2 helpers (Blackwell FFMA2 — only reachable via PTX, see
// SASS_QUICKREF "patterns absent from ptxas output").
// b64 little-endian: .lo = lower address float.
// ---------------------------------------------------------------------------
__device__ __forceinline__ void fma2(unsigned long long& acc,
                                     unsigned long long a,
                                     unsigned long long b) {
    asm("fma.rn.f32x2 %0, %1, %2, %0;" : "+l"(acc) : "l"(a), "l"(b));
}

__device__ __forceinline__ unsigned long long dup_f32(float x) {
    unsigned long long r;
    unsigned u = __float_as_uint(x);
    asm("mov.b64 %0, {%1, %1};" : "=l"(r) : "r"(u));
    return r;
}

__device__ __forceinline__ float lo_f32(unsigned long long v) {
    return __uint_as_float((unsigned)v);
}
__device__ __forceinline__ float hi_f32(unsigned long long v) {
    return __uint_as_float((unsigned)(v >> 32));
}

// ---------------------------------------------------------------------------
// Kernel 1: fp32 SGEMM  C[M,128] = A[M,512] * B[512,128]
// 128x128 block tile, BK=16, 8x8 thread tile, 256 threads.
// Inner product uses FFMA2 (f32x2): accumulators are M-pairs, N operand
// duplicated into both SIMD lanes. Halves fma-pipe instruction count.
// ---------------------------------------------------------------------------
__global__ __launch_bounds__(256) void gemm_kernel(const float* __restrict__ A,
                                                   const float* __restrict__ B,
                                                   int M) {
    __shared__ float As[16][128];   // [k][m] (transposed store; m contiguous)
    __shared__ float Bs[16][128];   // [k][n]

    const int tid = threadIdx.x;
    const int tx = tid & 15;        // 0..15 (n-direction)
    const int ty = tid >> 4;        // 0..15 (m-direction)
    const int block_row = blockIdx.x * 128;

    // acc[ip][j] = packed {C[m0+2ip][n0+j], C[m0+2ip+1][n0+j]}
    unsigned long long acc[4][8];
#pragma unroll
    for (int i = 0; i < 4; i++)
#pragma unroll
        for (int j = 0; j < 8; j++) acc[i][j] = 0ULL;

    for (int k0 = 0; k0 < IN_FEAT; k0 += 16) {
        // Load A tile: 128 rows x 16 cols = 512 float4, 2 per thread.
#pragma unroll
        for (int t = 0; t < 2; t++) {
            int pos = tid + t * 256;       // 0..511
            int r   = pos >> 2;            // 0..127
            int c4  = pos & 3;             // which float4 of the 16-wide row
            int grow = block_row + r;
            float4 v = make_float4(0.f, 0.f, 0.f, 0.f);
            if (grow < M)
                v = *(const float4*)(A + (size_t)grow * IN_FEAT + k0 + c4 * 4);
            As[c4 * 4 + 0][r] = v.x;
            As[c4 * 4 + 1][r] = v.y;
            As[c4 * 4 + 2][r] = v.z;
            As[c4 * 4 + 3][r] = v.w;
        }
        // Load B tile: 16 rows x 128 cols = 512 float4, 2 per thread.
#pragma unroll
        for (int t = 0; t < 2; t++) {
            int pos = tid + t * 256;
            int r   = pos >> 5;            // 0..15
            int c4  = pos & 31;            // 0..31
            *(float4*)(&Bs[r][c4 * 4]) =
                *(const float4*)(B + (size_t)(k0 + r) * OUT_FEAT + c4 * 4);
        }
        __syncthreads();

#pragma unroll
        for (int k = 0; k < 16; k++) {
            // M-pairs: 8 consecutive floats -> 4 natural b64 pairs (32B-aligned).
            ulonglong2 mA = *(const ulonglong2*)&As[k][ty * 8];
            ulonglong2 mB = *(const ulonglong2*)&As[k][ty * 8 + 4];
            unsigned long long mp[4] = {mA.x, mA.y, mB.x, mB.y};

            // N operand: load 8 floats, duplicate each into both SIMD lanes.
            float4 b0 = *(const float4*)&Bs[k][tx * 8];
            float4 b1 = *(const float4*)&Bs[k][tx * 8 + 4];
            unsigned long long nd[8];
            nd[0] = dup_f32(b0.x); nd[1] = dup_f32(b0.y);
            nd[2] = dup_f32(b0.z); nd[3] = dup_f32(b0.w);
            nd[4] = dup_f32(b1.x); nd[5] = dup_f32(b1.y);
            nd[6] = dup_f32(b1.z); nd[7] = dup_f32(b1.w);

#pragma unroll
            for (int ip = 0; ip < 4; ip++)
#pragma unroll
                for (int j = 0; j < 8; j++)
                    fma2(acc[ip][j], mp[ip], nd[j]);
        }
        __syncthreads();
    }

    // Store to scratch g_x. Pair ip holds rows (2ip) [lo] and (2ip+1) [hi].
#pragma unroll
    for (int ip = 0; ip < 4; ip++) {
        int r0 = block_row + ty * 8 + 2 * ip;
        int r1 = r0 + 1;
        if (r0 < M) {
            float4 v0 = make_float4(lo_f32(acc[ip][0]), lo_f32(acc[ip][1]),
                                    lo_f32(acc[ip][2]), lo_f32(acc[ip][3]));
            float4 v1 = make_float4(lo_f32(acc[ip][4]), lo_f32(acc[ip][5]),
                                    lo_f32(acc[ip][6]), lo_f32(acc[ip][7]));
            *(float4*)(g_x + (size_t)r0 * OUT_FEAT + tx * 8)     = v0;
            *(float4*)(g_x + (size_t)r0 * OUT_FEAT + tx * 8 + 4) = v1;
        }
        if (r1 < M) {
            float4 v0 = make_float4(hi_f32(acc[ip][0]), hi_f32(acc[ip][1]),
                                    hi_f32(acc[ip][2]), hi_f32(acc[ip][3]));
            float4 v1 = make_float4(hi_f32(acc[ip][4]), hi_f32(acc[ip][5]),
                                    hi_f32(acc[ip][6]), hi_f32(acc[ip][7]));
            *(float4*)(g_x + (size_t)r1 * OUT_FEAT + tx * 8)     = v0;
            *(float4*)(g_x + (size_t)r1 * OUT_FEAT + tx * 8 + 4) = v1;
        }
    }
}

// ---------------------------------------------------------------------------
// Kernel 2: build CSR row_ptr from sorted rows via binary search.
// ---------------------------------------------------------------------------
__global__ void build_rowptr_kernel(const int* __restrict__ rows) {
    int i = blockIdx.x * blockDim.x + threadIdx.x;
    if (i > N_NODES) return;
    int lo = 0, hi = N_EDGES;
    while (lo < hi) {
        int mid = (lo + hi) >> 1;
        if (rows[mid] < i) lo = mid + 1; else hi = mid;
    }
    g_row_ptr[i] = lo;
}

// ---------------------------------------------------------------------------
// Kernel 3: SpMM + multispike. One warp per output row; each lane owns a
// float4 (4 features). Gathers hit L2 (x table is 25.6 MB, fits 126 MB L2).
// ---------------------------------------------------------------------------
__device__ __forceinline__ float multispike(float x) {
    return floorf(fminf(fmaxf(4.0f * x, 0.0f), 4.0f) + 0.5f) * 0.25f;
}

__global__ __launch_bounds__(256) void spmm_kernel(const int* __restrict__ cols,
                                                   const float* __restrict__ ew,
                                                   float* __restrict__ out) {
    int gw   = (blockIdx.x * blockDim.x + threadIdx.x) >> 5;  // global warp = row
    int lane = threadIdx.x & 31;
    if (gw >= N_NODES) return;

    int s = g_row_ptr[gw];
    int e = g_row_ptr[gw + 1];

    const float4* __restrict__ xb = (const float4*)g_x;  // 32 float4 per row

    float ax = 0.f, ay = 0.f, az = 0.f, aw = 0.f;
    int i = s;
    for (; i + 1 < e; i += 2) {
        int   c0 = __ldg(cols + i);
        int   c1 = __ldg(cols + i + 1);
        float w0 = __ldg(ew + i);
        float w1 = __ldg(ew + i + 1);
        float4 v0 = __ldg(xb + (size_t)c0 * 32 + lane);
        float4 v1 = __ldg(xb + (size_t)c1 * 32 + lane);
        ax += w0 * v0.x; ay += w0 * v0.y; az += w0 * v0.z; aw += w0 * v0.w;
        ax += w1 * v1.x; ay += w1 * v1.y; az += w1 * v1.z; aw += w1 * v1.w;
    }
    if (i < e) {
        int   c0 = __ldg(cols + i);
        float w0 = __ldg(ew + i);
        float4 v0 = __ldg(xb + (size_t)c0 * 32 + lane);
        ax += w0 * v0.x; ay += w0 * v0.y; az += w0 * v0.z; aw += w0 * v0.w;
    }

    float4 r;
    r.x = multispike(ax);
    r.y = multispike(ay);
    r.z = multispike(az);
    r.w = multispike(aw);
    ((float4*)out)[(size_t)gw * 32 + lane] = r;
}

// ---------------------------------------------------------------------------
// Launch
// ---------------------------------------------------------------------------
extern "C" void kernel_launch(void* const* d_in, const int* in_sizes, int n_in,
                              void* d_out, int out_size) {
    const float* feat   = (const float*)d_in[0];   // [50000, 512]
    const float* weight = (const float*)d_in[1];   // [512, 128]
    const int*   rows   = (const int*)  d_in[2];   // [800000] sorted
    const int*   cols   = (const int*)  d_in[3];   // [800000]
    const float* ew     = (const float*)d_in[4];   // [800000]
    float* out = (float*)d_out;                    // [50000, 128]

    // 1) GEMM into scratch
    int gemm_blocks = (N_NODES + 127) / 128;       // 391
    gemm_kernel<<<gemm_blocks, 256>>>(feat, weight, N_NODES);

    // 2) CSR row pointers
    build_rowptr_kernel<<<(N_NODES + 1 + 255) / 256, 256>>>(rows);

    // 3) SpMM + activation: one warp per row
    int total_warps = N_NODES;
    int spmm_blocks = (total_warps * 32 + 255) / 256;  // 6250
    spmm_kernel<<<spmm_blocks, 256>>>(cols, ew, out);
}

// round 8
// speedup vs baseline: 1.1271x; 1.1135x over previous
#include <cuda_runtime.h>

#define N_NODES 50000
#define N_EDGES 800000
#define IN_FEAT 512
#define OUT_FEAT 128

// Scratch (no allocs allowed): intermediate x = feat @ W, and CSR row pointers.
__device__ float g_x[(size_t)N_NODES * OUT_FEAT];   // 25.6 MB
__device__ int   g_row_ptr[N_NODES + 1];

// ---------------------------------------------------------------------------
// 3xTF32 helpers
// ---------------------------------------------------------------------------
__device__ __forceinline__ void split_tf32(float a, unsigned& hi, unsigned& lo) {
    unsigned h;
    asm("cvt.rna.tf32.f32 %0, %1;" : "=r"(h) : "f"(a));
    float l = a - __uint_as_float(h);   // exact (Dekker split)
    unsigned lw;
    asm("cvt.rna.tf32.f32 %0, %1;" : "=r"(lw) : "f"(l));
    hi = h; lo = lw;
}

__device__ __forceinline__ void mma_tf32(float* d, const unsigned* a, const unsigned* b) {
    asm volatile(
        "mma.sync.aligned.m16n8k8.row.col.f32.tf32.tf32.f32 "
        "{%0,%1,%2,%3}, {%4,%5,%6,%7}, {%8,%9}, {%0,%1,%2,%3};"
        : "+f"(d[0]), "+f"(d[1]), "+f"(d[2]), "+f"(d[3])
        : "r"(a[0]), "r"(a[1]), "r"(a[2]), "r"(a[3]), "r"(b[0]), "r"(b[1]));
}

// ---------------------------------------------------------------------------
// Kernel 1: 3xTF32 tensor-core GEMM  C[M,128] = A[M,512] * B[512,128]
// CTA tile 128x128, BK=16, 256 threads = 8 warps (4 in M x 2 in N).
// Warp tile 32(M) x 64(N) = 2 m16-tiles x 8 n8-tiles. K split hi/lo in smem.
// Smem layouts chosen conflict-free for the m16n8k8 fragment pattern:
//   A: [m][k] stride 20  (bank = (20*gid + tig) % 32 -> 32 distinct)
//   B: [k][n] stride 136 (bank = (8*tig + gid) % 32  -> 32 distinct)
// ---------------------------------------------------------------------------
#define BK 16
#define A_STRIDE 20
#define B_STRIDE 136

__global__ __launch_bounds__(256, 2) void gemm_kernel(const float* __restrict__ A,
                                                      const float* __restrict__ B,
                                                      int M) {
    __shared__ unsigned As_hi[128 * A_STRIDE];
    __shared__ unsigned As_lo[128 * A_STRIDE];
    __shared__ unsigned Bs_hi[BK * B_STRIDE];
    __shared__ unsigned Bs_lo[BK * B_STRIDE];

    const int tid  = threadIdx.x;
    const int wid  = tid >> 5;
    const int lane = tid & 31;
    const int gid  = lane >> 2;     // 0..7
    const int tig  = lane & 3;      // 0..3
    const int wm   = wid >> 1;      // 0..3 (M direction)
    const int wn   = wid & 1;       // 0..1 (N direction)
    const int block_row = blockIdx.x * 128;

    // Staging coordinates
    const int sa_m    = tid >> 1;       // 0..127
    const int sa_half = tid & 1;        // 0/1 -> k offset 0/8
    const int sb_r    = tid >> 4;       // 0..15 (k)
    const int sb_c    = tid & 15;       // 0..15 -> n offset *8

    float acc[2][8][4];
#pragma unroll
    for (int mt = 0; mt < 2; mt++)
#pragma unroll
        for (int nt = 0; nt < 8; nt++)
#pragma unroll
            for (int r = 0; r < 4; r++) acc[mt][nt][r] = 0.0f;

    for (int kb = 0; kb < IN_FEAT / BK; kb++) {
        const int k0 = kb * BK;

        // ---- Stage A tile [128 x 16] -> hi/lo, [m][k] layout ----
        {
            float4 v0 = make_float4(0.f, 0.f, 0.f, 0.f);
            float4 v1 = v0;
            int grow = block_row + sa_m;
            if (grow < M) {
                const float4* src = (const float4*)(A + (size_t)grow * IN_FEAT + k0 + sa_half * 8);
                v0 = src[0];
                v1 = src[1];
            }
            uint4 h0, l0, h1, l1;
            split_tf32(v0.x, h0.x, l0.x); split_tf32(v0.y, h0.y, l0.y);
            split_tf32(v0.z, h0.z, l0.z); split_tf32(v0.w, h0.w, l0.w);
            split_tf32(v1.x, h1.x, l1.x); split_tf32(v1.y, h1.y, l1.y);
            split_tf32(v1.z, h1.z, l1.z); split_tf32(v1.w, h1.w, l1.w);
            int base = sa_m * A_STRIDE + sa_half * 8;
            *(uint4*)(As_hi + base)     = h0;
            *(uint4*)(As_hi + base + 4) = h1;
            *(uint4*)(As_lo + base)     = l0;
            *(uint4*)(As_lo + base + 4) = l1;
        }
        // ---- Stage B tile [16 x 128] -> hi/lo, [k][n] layout ----
        {
            const float4* src = (const float4*)(B + (size_t)(k0 + sb_r) * OUT_FEAT + sb_c * 8);
            float4 v0 = src[0];
            float4 v1 = src[1];
            uint4 h0, l0, h1, l1;
            split_tf32(v0.x, h0.x, l0.x); split_tf32(v0.y, h0.y, l0.y);
            split_tf32(v0.z, h0.z, l0.z); split_tf32(v0.w, h0.w, l0.w);
            split_tf32(v1.x, h1.x, l1.x); split_tf32(v1.y, h1.y, l1.y);
            split_tf32(v1.z, h1.z, l1.z); split_tf32(v1.w, h1.w, l1.w);
            int base = sb_r * B_STRIDE + sb_c * 8;
            *(uint4*)(Bs_hi + base)     = h0;
            *(uint4*)(Bs_hi + base + 4) = h1;
            *(uint4*)(Bs_lo + base)     = l0;
            *(uint4*)(Bs_lo + base + 4) = l1;
        }
        __syncthreads();

        // ---- Compute: 2 k-steps of 8 ----
#pragma unroll
        for (int ks = 0; ks < 2; ks++) {
            const int kk = ks * 8;
            unsigned ah[2][4], al[2][4];
#pragma unroll
            for (int mt = 0; mt < 2; mt++) {
                int m0 = (wm * 32 + mt * 16 + gid) * A_STRIDE;
                int m1 = m0 + 8 * A_STRIDE;
                ah[mt][0] = As_hi[m0 + kk + tig];
                ah[mt][1] = As_hi[m1 + kk + tig];
                ah[mt][2] = As_hi[m0 + kk + tig + 4];
                ah[mt][3] = As_hi[m1 + kk + tig + 4];
                al[mt][0] = As_lo[m0 + kk + tig];
                al[mt][1] = As_lo[m1 + kk + tig];
                al[mt][2] = As_lo[m0 + kk + tig + 4];
                al[mt][3] = As_lo[m1 + kk + tig + 4];
            }
#pragma unroll
            for (int nt = 0; nt < 8; nt++) {
                int nc = wn * 64 + nt * 8 + gid;
                unsigned bh[2], bl[2];
                bh[0] = Bs_hi[(kk + tig) * B_STRIDE + nc];
                bh[1] = Bs_hi[(kk + tig + 4) * B_STRIDE + nc];
                bl[0] = Bs_lo[(kk + tig) * B_STRIDE + nc];
                bl[1] = Bs_lo[(kk + tig + 4) * B_STRIDE + nc];
#pragma unroll
                for (int mt = 0; mt < 2; mt++) {
                    mma_tf32(acc[mt][nt], ah[mt], bl);   // hi x lo
                    mma_tf32(acc[mt][nt], al[mt], bh);   // lo x hi
                    mma_tf32(acc[mt][nt], ah[mt], bh);   // hi x hi
                }
            }
        }
        __syncthreads();
    }

    // ---- Epilogue: fragment layout c0,c1 at (gid, 2tig..+1); c2,c3 at (gid+8, ..) ----
#pragma unroll
    for (int mt = 0; mt < 2; mt++) {
#pragma unroll
        for (int nt = 0; nt < 8; nt++) {
            int row0 = block_row + wm * 32 + mt * 16 + gid;
            int col  = wn * 64 + nt * 8 + 2 * tig;
            if (row0 < M) {
                float2 v = make_float2(acc[mt][nt][0], acc[mt][nt][1]);
                *(float2*)(g_x + (size_t)row0 * OUT_FEAT + col) = v;
            }
            int row1 = row0 + 8;
            if (row1 < M) {
                float2 v = make_float2(acc[mt][nt][2], acc[mt][nt][3]);
                *(float2*)(g_x + (size_t)row1 * OUT_FEAT + col) = v;
            }
        }
    }
}

// ---------------------------------------------------------------------------
// Kernel 2: build CSR row_ptr from sorted rows via binary search.
// ---------------------------------------------------------------------------
__global__ void build_rowptr_kernel(const int* __restrict__ rows) {
    int i = blockIdx.x * blockDim.x + threadIdx.x;
    if (i > N_NODES) return;
    int lo = 0, hi = N_EDGES;
    while (lo < hi) {
        int mid = (lo + hi) >> 1;
        if (rows[mid] < i) lo = mid + 1; else hi = mid;
    }
    g_row_ptr[i] = lo;
}

// ---------------------------------------------------------------------------
// Kernel 3: SpMM + multispike. One warp per output row; each lane owns a
// float4 (4 features). Gathers hit L2 (x table is 25.6 MB, fits 126 MB L2).
// ---------------------------------------------------------------------------
__device__ __forceinline__ float multispike(float x) {
    return floorf(fminf(fmaxf(4.0f * x, 0.0f), 4.0f) + 0.5f) * 0.25f;
}

__global__ __launch_bounds__(256) void spmm_kernel(const int* __restrict__ cols,
                                                   const float* __restrict__ ew,
                                                   float* __restrict__ out) {
    int gw   = (blockIdx.x * blockDim.x + threadIdx.x) >> 5;  // global warp = row
    int lane = threadIdx.x & 31;
    if (gw >= N_NODES) return;

    int s = g_row_ptr[gw];
    int e = g_row_ptr[gw + 1];

    const float4* __restrict__ xb = (const float4*)g_x;  // 32 float4 per row

    float ax = 0.f, ay = 0.f, az = 0.f, aw = 0.f;
    int i = s;
    for (; i + 1 < e; i += 2) {
        int   c0 = __ldg(cols + i);
        int   c1 = __ldg(cols + i + 1);
        float w0 = __ldg(ew + i);
        float w1 = __ldg(ew + i + 1);
        float4 v0 = __ldg(xb + (size_t)c0 * 32 + lane);
        float4 v1 = __ldg(xb + (size_t)c1 * 32 + lane);
        ax += w0 * v0.x; ay += w0 * v0.y; az += w0 * v0.z; aw += w0 * v0.w;
        ax += w1 * v1.x; ay += w1 * v1.y; az += w1 * v1.z; aw += w1 * v1.w;
    }
    if (i < e) {
        int   c0 = __ldg(cols + i);
        float w0 = __ldg(ew + i);
        float4 v0 = __ldg(xb + (size_t)c0 * 32 + lane);
        ax += w0 * v0.x; ay += w0 * v0.y; az += w0 * v0.z; aw += w0 * v0.w;
    }

    float4 r;
    r.x = multispike(ax);
    r.y = multispike(ay);
    r.z = multispike(az);
    r.w = multispike(aw);
    ((float4*)out)[(size_t)gw * 32 + lane] = r;
}

// ---------------------------------------------------------------------------
// Launch
// ---------------------------------------------------------------------------
extern "C" void kernel_launch(void* const* d_in, const int* in_sizes, int n_in,
                              void* d_out, int out_size) {
    const float* feat   = (const float*)d_in[0];   // [50000, 512]
    const float* weight = (const float*)d_in[1];   // [512, 128]
    const int*   rows   = (const int*)  d_in[2];   // [800000] sorted
    const int*   cols   = (const int*)  d_in[3];   // [800000]
    const float* ew     = (const float*)d_in[4];   // [800000]
    float* out = (float*)d_out;                    // [50000, 128]

    // 1) GEMM into scratch (3xTF32 tensor cores)
    int gemm_blocks = (N_NODES + 127) / 128;       // 391
    gemm_kernel<<<gemm_blocks, 256>>>(feat, weight, N_NODES);

    // 2) CSR row pointers
    build_rowptr_kernel<<<(N_NODES + 1 + 255) / 256, 256>>>(rows);

    // 3) SpMM + activation: one warp per row
    int total_warps = N_NODES;
    int spmm_blocks = (total_warps * 32 + 255) / 256;  // 6250
    spmm_kernel<<<spmm_blocks, 256>>>(cols, ew, out);
}

// round 9
// speedup vs baseline: 1.3231x; 1.1739x over previous
#include <cuda_runtime.h>

#define N_NODES 50000
#define N_EDGES 800000
#define IN_FEAT 512
#define OUT_FEAT 128

// Scratch (no allocs allowed): intermediate x = feat @ W, and CSR row pointers.
__device__ float g_x[(size_t)N_NODES * OUT_FEAT];   // 25.6 MB
__device__ int   g_row_ptr[N_NODES + 1];

// ---------------------------------------------------------------------------
// 3xTF32 helpers
// ---------------------------------------------------------------------------
__device__ __forceinline__ void split_tf32(float a, unsigned& hi, unsigned& lo) {
    unsigned h;
    asm("cvt.rna.tf32.f32 %0, %1;" : "=r"(h) : "f"(a));
    float l = a - __uint_as_float(h);   // exact (Dekker split)
    unsigned lw;
    asm("cvt.rna.tf32.f32 %0, %1;" : "=r"(lw) : "f"(l));
    hi = h; lo = lw;
}

__device__ __forceinline__ void mma_tf32(float* d, const unsigned* a, const unsigned* b) {
    asm volatile(
        "mma.sync.aligned.m16n8k8.row.col.f32.tf32.tf32.f32 "
        "{%0,%1,%2,%3}, {%4,%5,%6,%7}, {%8,%9}, {%0,%1,%2,%3};"
        : "+f"(d[0]), "+f"(d[1]), "+f"(d[2]), "+f"(d[3])
        : "r"(a[0]), "r"(a[1]), "r"(a[2]), "r"(a[3]), "r"(b[0]), "r"(b[1]));
}

// cp.async 16B with zero-fill predication (src_bytes = 16 or 0).
__device__ __forceinline__ void cp_async16(void* smem_dst, const void* gsrc, int src_bytes) {
    unsigned saddr = (unsigned)__cvta_generic_to_shared(smem_dst);
    asm volatile("cp.async.cg.shared.global [%0], [%1], 16, %2;"
                 :: "r"(saddr), "l"(gsrc), "r"(src_bytes));
}
__device__ __forceinline__ void cp_commit() {
    asm volatile("cp.async.commit_group;");
}
template <int N>
__device__ __forceinline__ void cp_wait() {
    asm volatile("cp.async.wait_group %0;" :: "n"(N));
}

// ---------------------------------------------------------------------------
// Kernel 1: 3xTF32 tensor-core GEMM  C[M,128] = A[M,512] * B[512,128]
// CTA tile 128x128, BK=16, 256 threads = 8 warps (4 in M x 2 in N).
// Double-buffered cp.async pipeline; raw fp32 smem tiles; tf32 hi/lo split
// performed at fragment-load time (hidden under tensor-pipe shadow).
// Conflict-free layouts for the m16n8k8 fragment pattern:
//   A: [m][k] stride 20  (bank = (20*gid + tig) % 32 -> 32 distinct)
//   B: [k][n] stride 136 (bank = (8*tig + 8*nt + gid) % 32 -> distinct)
// ---------------------------------------------------------------------------
#define BK 16
#define NKB (IN_FEAT / BK)    // 32
#define A_STRIDE 20
#define B_STRIDE 136

__global__ __launch_bounds__(256, 2) void gemm_kernel(const float* __restrict__ A,
                                                      const float* __restrict__ B,
                                                      int M) {
    __shared__ float As[2][128 * A_STRIDE];   // 2 x 10240 B
    __shared__ float Bs[2][BK * B_STRIDE];    // 2 x 8704 B

    const int tid  = threadIdx.x;
    const int wid  = tid >> 5;
    const int lane = tid & 31;
    const int gid  = lane >> 2;     // 0..7
    const int tig  = lane & 3;      // 0..3
    const int wm   = wid >> 1;      // 0..3 (M direction)
    const int wn   = wid & 1;       // 0..1 (N direction)
    const int block_row = blockIdx.x * 128;

    // Staging coordinates
    const int sa_m    = tid >> 1;       // 0..127
    const int sa_half = tid & 1;        // 0/1 -> k offset 0/8
    const int sb_r    = tid >> 4;       // 0..15 (k)
    const int sb_c    = tid & 15;       // 0..15 -> n offset *8

    // Precompute staging addresses
    const int a_row     = block_row + sa_m;
    const int a_valid   = (a_row < M) ? 16 : 0;
    const int a_row_cl  = (a_row < M) ? a_row : (M - 1);   // always-valid address
    const float* a_base = A + (size_t)a_row_cl * IN_FEAT + sa_half * 8;
    float* a_dst0 = &As[0][sa_m * A_STRIDE + sa_half * 8];
    float* a_dst1 = &As[1][sa_m * A_STRIDE + sa_half * 8];
    const float* b_base = B + (size_t)sb_r * OUT_FEAT + sb_c * 8;
    float* b_dst0 = &Bs[0][sb_r * B_STRIDE + sb_c * 8];
    float* b_dst1 = &Bs[1][sb_r * B_STRIDE + sb_c * 8];

    float acc[2][8][4];
#pragma unroll
    for (int mt = 0; mt < 2; mt++)
#pragma unroll
        for (int nt = 0; nt < 8; nt++)
#pragma unroll
            for (int r = 0; r < 4; r++) acc[mt][nt][r] = 0.0f;

    // Prologue: stage k-block 0 into buffer 0
    {
        cp_async16(a_dst0,     a_base,     a_valid);
        cp_async16(a_dst0 + 4, a_base + 4, a_valid);
        cp_async16(b_dst0,     b_base,     16);
        cp_async16(b_dst0 + 4, b_base + 4, 16);
        cp_commit();
    }

    for (int kb = 0; kb < NKB; kb++) {
        const int buf = kb & 1;

        // Issue loads for next k-block into the other buffer, then wait for
        // the current block's group to land.
        if (kb + 1 < NKB) {
            const float* an = a_base + (kb + 1) * BK;
            const float* bn = b_base + (size_t)(kb + 1) * BK * OUT_FEAT;
            float* ad = buf ? a_dst0 : a_dst1;
            float* bd = buf ? b_dst0 : b_dst1;
            cp_async16(ad,     an,     a_valid);
            cp_async16(ad + 4, an + 4, a_valid);
            cp_async16(bd,     bn,     16);
            cp_async16(bd + 4, bn + 4, 16);
            cp_commit();
            cp_wait<1>();
        } else {
            cp_wait<0>();
        }
        __syncthreads();

        const float* __restrict__ Ab = As[buf];
        const float* __restrict__ Bb = Bs[buf];

#pragma unroll
        for (int ks = 0; ks < 2; ks++) {
            const int kk = ks * 8;
            unsigned ah[2][4], al[2][4];
#pragma unroll
            for (int mt = 0; mt < 2; mt++) {
                int m0 = (wm * 32 + mt * 16 + gid) * A_STRIDE;
                int m1 = m0 + 8 * A_STRIDE;
                float a0 = Ab[m0 + kk + tig];
                float a1 = Ab[m1 + kk + tig];
                float a2 = Ab[m0 + kk + tig + 4];
                float a3 = Ab[m1 + kk + tig + 4];
                split_tf32(a0, ah[mt][0], al[mt][0]);
                split_tf32(a1, ah[mt][1], al[mt][1]);
                split_tf32(a2, ah[mt][2], al[mt][2]);
                split_tf32(a3, ah[mt][3], al[mt][3]);
            }
#pragma unroll
            for (int nt = 0; nt < 8; nt++) {
                int nc = wn * 64 + nt * 8 + gid;
                float b0 = Bb[(kk + tig) * B_STRIDE + nc];
                float b1 = Bb[(kk + tig + 4) * B_STRIDE + nc];
                unsigned bh[2], bl[2];
                split_tf32(b0, bh[0], bl[0]);
                split_tf32(b1, bh[1], bl[1]);
#pragma unroll
                for (int mt = 0; mt < 2; mt++) {
                    mma_tf32(acc[mt][nt], ah[mt], bl);   // hi x lo
                    mma_tf32(acc[mt][nt], al[mt], bh);   // lo x hi
                    mma_tf32(acc[mt][nt], ah[mt], bh);   // hi x hi
                }
            }
        }
        __syncthreads();
    }

    // ---- Epilogue: fragment layout c0,c1 at (gid, 2tig..+1); c2,c3 at (gid+8, ..) ----
#pragma unroll
    for (int mt = 0; mt < 2; mt++) {
#pragma unroll
        for (int nt = 0; nt < 8; nt++) {
            int row0 = block_row + wm * 32 + mt * 16 + gid;
            int col  = wn * 64 + nt * 8 + 2 * tig;
            if (row0 < M) {
                float2 v = make_float2(acc[mt][nt][0], acc[mt][nt][1]);
                *(float2*)(g_x + (size_t)row0 * OUT_FEAT + col) = v;
            }
            int row1 = row0 + 8;
            if (row1 < M) {
                float2 v = make_float2(acc[mt][nt][2], acc[mt][nt][3]);
                *(float2*)(g_x + (size_t)row1 * OUT_FEAT + col) = v;
            }
        }
    }
}

// ---------------------------------------------------------------------------
// Kernel 2: build CSR row_ptr from sorted rows via binary search.
// ---------------------------------------------------------------------------
__global__ void build_rowptr_kernel(const int* __restrict__ rows) {
    int i = blockIdx.x * blockDim.x + threadIdx.x;
    if (i > N_NODES) return;
    int lo = 0, hi = N_EDGES;
    while (lo < hi) {
        int mid = (lo + hi) >> 1;
        if (rows[mid] < i) lo = mid + 1; else hi = mid;
    }
    g_row_ptr[i] = lo;
}

// ---------------------------------------------------------------------------
// Kernel 3: SpMM + multispike. One warp per output row; each lane owns a
// float4 (4 features). Gathers hit L2 (x table is 25.6 MB, fits 126 MB L2).
// ---------------------------------------------------------------------------
__device__ __forceinline__ float multispike(float x) {
    return floorf(fminf(fmaxf(4.0f * x, 0.0f), 4.0f) + 0.5f) * 0.25f;
}

__global__ __launch_bounds__(256) void spmm_kernel(const int* __restrict__ cols,
                                                   const float* __restrict__ ew,
                                                   float* __restrict__ out) {
    int gw   = (blockIdx.x * blockDim.x + threadIdx.x) >> 5;  // global warp = row
    int lane = threadIdx.x & 31;
    if (gw >= N_NODES) return;

    int s = g_row_ptr[gw];
    int e = g_row_ptr[gw + 1];

    const float4* __restrict__ xb = (const float4*)g_x;  // 32 float4 per row

    float ax = 0.f, ay = 0.f, az = 0.f, aw = 0.f;
    int i = s;
    for (; i + 1 < e; i += 2) {
        int   c0 = __ldg(cols + i);
        int   c1 = __ldg(cols + i + 1);
        float w0 = __ldg(ew + i);
        float w1 = __ldg(ew + i + 1);
        float4 v0 = __ldg(xb + (size_t)c0 * 32 + lane);
        float4 v1 = __ldg(xb + (size_t)c1 * 32 + lane);
        ax += w0 * v0.x; ay += w0 * v0.y; az += w0 * v0.z; aw += w0 * v0.w;
        ax += w1 * v1.x; ay += w1 * v1.y; az += w1 * v1.z; aw += w1 * v1.w;
    }
    if (i < e) {
        int   c0 = __ldg(cols + i);
        float w0 = __ldg(ew + i);
        float4 v0 = __ldg(xb + (size_t)c0 * 32 + lane);
        ax += w0 * v0.x; ay += w0 * v0.y; az += w0 * v0.z; aw += w0 * v0.w;
    }

    float4 r;
    r.x = multispike(ax);
    r.y = multispike(ay);
    r.z = multispike(az);
    r.w = multispike(aw);
    ((float4*)out)[(size_t)gw * 32 + lane] = r;
}

// ---------------------------------------------------------------------------
// Launch
// ---------------------------------------------------------------------------
extern "C" void kernel_launch(void* const* d_in, const int* in_sizes, int n_in,
                              void* d_out, int out_size) {
    const float* feat   = (const float*)d_in[0];   // [50000, 512]
    const float* weight = (const float*)d_in[1];   // [512, 128]
    const int*   rows   = (const int*)  d_in[2];   // [800000] sorted
    const int*   cols   = (const int*)  d_in[3];   // [800000]
    const float* ew     = (const float*)d_in[4];   // [800000]
    float* out = (float*)d_out;                    // [50000, 128]

    // 1) CSR row pointers (tiny, independent)
    build_rowptr_kernel<<<(N_NODES + 1 + 255) / 256, 256>>>(rows);

    // 2) GEMM into scratch (3xTF32 tensor cores, double-buffered cp.async)
    int gemm_blocks = (N_NODES + 127) / 128;       // 391
    gemm_kernel<<<gemm_blocks, 256>>>(feat, weight, N_NODES);

    // 3) SpMM + activation: one warp per row
    int total_warps = N_NODES;
    int spmm_blocks = (total_warps * 32 + 255) / 256;  // 6250
    spmm_kernel<<<spmm_blocks, 256>>>(cols, ew, out);
}